// round 3
// baseline (speedup 1.0000x reference)
#include <cuda_runtime.h>

// CollisionLoss, role-split version.
// pos [B=65536, N=24, 3] f32 -> scalar f32.
// Per batch, over masked pairs (i<j, i>=1, skip (2,3)):
//   sq = |p_i-p_j|^2 ; if sq < 0.25: sum += exp(-4*sq); cnt++
// out = (cnt>0 ? sum/cnt : 0) + 1e-6
// Coords pre-scaled (at staging) by s = sqrt(4*log2(e)) so term = 2^(-sq')
// (raw EX2) and the test is sq' < 1.44269504.
// 4 threads per batch: role = warp id (0..3), lane = batch within block.
//   role0: pairs within A={1..12}   (65 pairs, skip (2,3))
//   role1: pairs within B={13..23}  (55 pairs)
//   role2: i in {1..6}  x B         (66 pairs)
//   role3: i in {7..12} x B         (66 pairs)

#define THREADS 128
#define BATCH_PER_BLOCK 32
#define PTS 24
#define FLOATS_PER (PTS * 3)   // 72
#define SMEM_STRIDE 73         // 73 mod 32 = 9, coprime with 32 -> conflict-free rows
#define MAX_BLOCKS 2048

__device__ float g_psum[MAX_BLOCKS];
__device__ float g_pcnt[MAX_BLOCKS];
__device__ unsigned int g_ticket = 0;

#define PAIR(ax, ay, az, bx, by, bz)                                \
    do {                                                            \
        float d0 = (ax) - (bx);                                     \
        float d1 = (ay) - (by);                                     \
        float d2 = (az) - (bz);                                     \
        float nsq = d0 * -d0;                                       \
        nsq = fmaf(d1, -d1, nsq);                                   \
        nsq = fmaf(d2, -d2, nsq);                                   \
        float e;                                                    \
        asm("ex2.approx.f32 %0, %1;" : "=f"(e) : "f"(nsq));         \
        if (nsq > -1.44269504f) { lsum += e; lcnt += 1; }           \
    } while (0)

__global__ __launch_bounds__(THREADS, 8)
void collision_role_kernel(const float* __restrict__ pos, float* __restrict__ out, int B) {
    __shared__ float sm[BATCH_PER_BLOCK * SMEM_STRIDE];
    __shared__ float wsum[THREADS / 32];
    __shared__ int   wcnt[THREADS / 32];
    __shared__ bool  amLast;

    const int tid   = threadIdx.x;
    const int role  = tid >> 5;          // warp id = role, uniform per warp
    const int lane  = tid & 31;          // batch within block
    const int bbase = blockIdx.x * BATCH_PER_BLOCK;
    const int valid = min(BATCH_PER_BLOCK, B - bbase);

    // ---- Stage: coalesced float4 gmem -> padded smem, scaled once here ----
    {
        const float SCALE = 2.4022448929611436f;   // sqrt(4 * log2(e))
        const float4* src4 = reinterpret_cast<const float4*>(pos + (size_t)bbase * FLOATS_PER);
        const int n4 = (valid * FLOATS_PER) >> 2;  // 72 % 4 == 0, rows stay intact
        for (int q = tid; q < n4; q += THREADS) {
            float4 v = src4[q];
            int g = q << 2;
            int b = g / FLOATS_PER;
            int w = g - b * FLOATS_PER;
            float* d = &sm[b * SMEM_STRIDE + w];
            d[0] = v.x * SCALE; d[1] = v.y * SCALE;
            d[2] = v.z * SCALE; d[3] = v.w * SCALE;
        }
    }
    __syncthreads();

    float lsum = 0.0f;
    int   lcnt = 0;

    if (lane < valid) {
        const float* row = &sm[lane * SMEM_STRIDE];   // conflict-free across lanes

        if (role == 0) {
            // pairs within A = {1..12}, skip (2,3)
            float px[13], py[13], pz[13];
            #pragma unroll
            for (int i = 1; i <= 12; i++) {
                px[i] = row[i * 3 + 0]; py[i] = row[i * 3 + 1]; pz[i] = row[i * 3 + 2];
            }
            #pragma unroll
            for (int i = 1; i <= 12; i++) {
                #pragma unroll
                for (int j = i + 1; j <= 12; j++) {
                    if (i == 2 && j == 3) continue;   // compile-time elided
                    PAIR(px[i], py[i], pz[i], px[j], py[j], pz[j]);
                }
            }
        } else if (role == 1) {
            // pairs within B = {13..23}
            float px[11], py[11], pz[11];
            #pragma unroll
            for (int j = 0; j < 11; j++) {
                int p = 13 + j;
                px[j] = row[p * 3 + 0]; py[j] = row[p * 3 + 1]; pz[j] = row[p * 3 + 2];
            }
            #pragma unroll
            for (int i = 0; i < 11; i++) {
                #pragma unroll
                for (int j = i + 1; j < 11; j++) {
                    PAIR(px[i], py[i], pz[i], px[j], py[j], pz[j]);
                }
            }
        } else {
            // cross: i-range x B; role2: i in {1..6}, role3: i in {7..12}
            float bx[11], by[11], bz[11];
            #pragma unroll
            for (int j = 0; j < 11; j++) {
                int p = 13 + j;
                bx[j] = row[p * 3 + 0]; by[j] = row[p * 3 + 1]; bz[j] = row[p * 3 + 2];
            }
            const int i0 = (role == 2) ? 1 : 7;
            #pragma unroll
            for (int k = 0; k < 6; k++) {
                int i = i0 + k;
                float ax = row[i * 3 + 0];
                float ay = row[i * 3 + 1];
                float az = row[i * 3 + 2];
                #pragma unroll
                for (int j = 0; j < 11; j++) {
                    PAIR(ax, ay, az, bx[j], by[j], bz[j]);
                }
            }
        }
    }

    // ---- Block reduce ----
    #pragma unroll
    for (int o = 16; o > 0; o >>= 1) {
        lsum += __shfl_down_sync(0xffffffffu, lsum, o);
        lcnt += __shfl_down_sync(0xffffffffu, lcnt, o);
    }
    if (lane == 0) { wsum[role] = lsum; wcnt[role] = lcnt; }
    __syncthreads();
    if (tid == 0) {
        float s = 0.0f; int c = 0;
        #pragma unroll
        for (int w = 0; w < THREADS / 32; w++) { s += wsum[w]; c += wcnt[w]; }
        g_psum[blockIdx.x] = s;
        g_pcnt[blockIdx.x] = (float)c;
        __threadfence();
        unsigned int t = atomicAdd(&g_ticket, 1u);
        amLast = (t == gridDim.x - 1);
    }
    __syncthreads();

    // ---- Last block finalizes ----
    if (amLast) {
        const int nb = gridDim.x;
        float s = 0.0f, c = 0.0f;
        for (int i = tid; i < nb; i += THREADS) {
            s += g_psum[i];
            c += g_pcnt[i];
        }
        #pragma unroll
        for (int o = 16; o > 0; o >>= 1) {
            s += __shfl_down_sync(0xffffffffu, s, o);
            c += __shfl_down_sync(0xffffffffu, c, o);
        }
        if (lane == 0) { wsum[role] = s; wcnt[role] = __float_as_int(c); }
        __syncthreads();
        if (tid == 0) {
            float ts = 0.0f, tc = 0.0f;
            #pragma unroll
            for (int w = 0; w < THREADS / 32; w++) {
                ts += wsum[w];
                tc += __int_as_float(wcnt[w]);
            }
            float total = (tc > 0.0f) ? (ts / fmaxf(tc, 1.0f)) : 0.0f;
            out[0] = total + 1e-6f;
            g_ticket = 0;   // reset for next graph replay
        }
    }
}

extern "C" void kernel_launch(void* const* d_in, const int* in_sizes, int n_in,
                              void* d_out, int out_size) {
    const float* pos = (const float*)d_in[0];
    const int B = in_sizes[0] / FLOATS_PER;
    int nblocks = (B + BATCH_PER_BLOCK - 1) / BATCH_PER_BLOCK;   // 2048 for B=65536
    if (nblocks > MAX_BLOCKS) nblocks = MAX_BLOCKS;
    collision_role_kernel<<<nblocks, THREADS>>>(pos, (float*)d_out, B);
}